// round 15
// baseline (speedup 1.0000x reference)
#include <cuda_runtime.h>
#include <math.h>

#define BATCH    16384
#define MAZE_LEN 3844
#define NWARPS   4096          // each warp does rows w, w+4096, w+8192, w+12288
#define GRID     512           // 256-thread CTAs, 8 warps each

// 120 needed columns per row (3721 double-counted), all reciprocal-summed:
//   -log(clip(prod, e^-90)) == min(log(S - 127), 90)
// (S includes 8 dummy 1.0-reciprocals from inactive mid lanes per row.)
//
// Floor model (ledger-validated): warm replays ~L2-resident; time =
// line-granular L2->L1 transfer of 88 MB (~7.5us at LTS cap) + launch
// overhead. This round: replace {memset node + per-CTA same-address atomics}
// with {per-CTA slot STG + tiny reduce kernel} — no atomics, no memset.

__device__ float g_partials[GRID];   // written unconditionally each launch

__device__ __forceinline__ float fast_rcp(float x) {
    float r;
    asm("rcp.approx.ftz.f32 %0, %1;" : "=f"(r) : "f"(x));
    return r;
}

// Fold 4 reciprocals into one MUFU.RCP.
__device__ __forceinline__ float fold4(float h, float t, float m0, float m1) {
    const float a   = h * t;
    const float b   = m0 * m1;
    const float num = (h + t) * b + (m0 + m1) * a;
    return num * fast_rcp(a * b);
}

__global__ __launch_bounds__(256)
void fuzzy_chain_kernel(const float* __restrict__ maze)
{
    const int warp_local  = threadIdx.x >> 5;                 // 0..7
    const int warp_global = blockIdx.x * 8 + warp_local;
    const int lane        = threadIdx.x & 31;

    // ---- per-lane scalar indices (shared by all 4 rows) ------------------
    int h_i = 4 * lane + 1;
    if (lane == 0) h_i = 1;
    if (lane == 1) h_i = 6;

    int t_i = 3717 + 4 * lane;
    if (lane == 29) t_i = 3721;                   // duplicate 3721
    if (lane == 30) t_i = 3839;
    if (lane == 31) t_i = 3841;

    const int k     = lane >> 1;
    const int comp  = lane & 1;
    const int p1    = 16 + k;
    const bool act1 = (p1 < 28);
    const int m0_i  = 124 * k + 245 + 4 * comp;
    const int m1_i  = 124 * (act1 ? p1 : 27) + 245 + 4 * comp;

    const float* __restrict__ r0 = maze + (size_t)warp_global * MAZE_LEN;
    const float* __restrict__ r1 = r0 + (size_t)NWARPS * MAZE_LEN;
    const float* __restrict__ r2 = r1 + (size_t)NWARPS * MAZE_LEN;
    const float* __restrict__ r3 = r2 + (size_t)NWARPS * MAZE_LEN;

    // ---- front-batch all 16 scalar loads (LDG.E.NC) ----------------------
    const float h0 = __ldg(r0 + h_i), t0 = __ldg(r0 + t_i);
    const float a0 = __ldg(r0 + m0_i), b0l = __ldg(r0 + m1_i);
    const float h1 = __ldg(r1 + h_i), t1 = __ldg(r1 + t_i);
    const float a1 = __ldg(r1 + m0_i), b1l = __ldg(r1 + m1_i);
    const float h2 = __ldg(r2 + h_i), t2 = __ldg(r2 + t_i);
    const float a2 = __ldg(r2 + m0_i), b2l = __ldg(r2 + m1_i);
    const float h3 = __ldg(r3 + h_i), t3 = __ldg(r3 + t_i);
    const float a3 = __ldg(r3 + m0_i), b3l = __ldg(r3 + m1_i);

    const float b0 = act1 ? b0l : 1.0f;           // dummy -> rcp(1)=1, in constant
    const float b1 = act1 ? b1l : 1.0f;
    const float b2 = act1 ? b2l : 1.0f;
    const float b3 = act1 ? b3l : 1.0f;

    float s0 = fold4(h0, t0, a0, b0);
    float s1 = fold4(h1, t1, a1, b1);
    float s2 = fold4(h2, t2, a2, b2);
    float s3 = fold4(h3, t3, a3, b3);

    // ---- warp reduction of all 4 rows' S ---------------------------------
    #pragma unroll
    for (int off = 16; off > 0; off >>= 1) {
        s0 += __shfl_xor_sync(0xffffffffu, s0, off);
        s1 += __shfl_xor_sync(0xffffffffu, s1, off);
        s2 += __shfl_xor_sync(0xffffffffu, s2, off);
        s3 += __shfl_xor_sync(0xffffffffu, s3, off);
    }

    __shared__ float warp_vals[8];
    if (lane == 0) {
        // x==0 -> inf -> __logf(inf)=inf -> fminf -> 90; NaN -> fminf -> 90.
        const float v0 = fminf(__logf(s0 - 127.0f), 90.0f);
        const float v1 = fminf(__logf(s1 - 127.0f), 90.0f);
        const float v2 = fminf(__logf(s2 - 127.0f), 90.0f);
        const float v3 = fminf(__logf(s3 - 127.0f), 90.0f);
        warp_vals[warp_local] = (v0 + v1) + (v2 + v3);
    }
    __syncthreads();

    if (threadIdx.x == 0) {
        float t = 0.0f;
        #pragma unroll
        for (int i = 0; i < 8; i++) t += warp_vals[i];
        g_partials[blockIdx.x] = t;               // plain STG, no atomic
    }
}

// Second node: deterministic tree-sum of the 512 partials.
__global__ __launch_bounds__(128)
void reduce_kernel(float* __restrict__ out)
{
    const int tid = threadIdx.x;
    float s = 0.0f;
    #pragma unroll
    for (int i = 0; i < GRID / 128; i++)          // 4 slots per thread
        s += g_partials[tid + 128 * i];

    #pragma unroll
    for (int off = 16; off > 0; off >>= 1)
        s += __shfl_xor_sync(0xffffffffu, s, off);

    __shared__ float wv[4];
    if ((tid & 31) == 0) wv[tid >> 5] = s;
    __syncthreads();
    if (tid == 0)
        out[0] = ((wv[0] + wv[1]) + (wv[2] + wv[3])) * (1.0f / (float)BATCH);
}

extern "C" void kernel_launch(void* const* d_in, const int* in_sizes, int n_in,
                              void* d_out, int out_size)
{
    const float* maze = (const float*)d_in[0];
    float*       out  = (float*)d_out;

    fuzzy_chain_kernel<<<GRID, 256>>>(maze);
    reduce_kernel<<<1, 128>>>(out);
}

// round 16
// speedup vs baseline: 1.0852x; 1.0852x over previous
#include <cuda_runtime.h>
#include <math.h>

#define BATCH    16384
#define MAZE_LEN 3844
#define NWARPS   4096          // each warp does rows w, w+4096, w+8192, w+12288

// FINAL (ledger-validated best, 10.11us):
//   math:   -log(clip(chain-AND, e^-90)) == min(log(S - 127), 90),
//           S = sum of reciprocals of the 120 gathered columns
//           (+8 dummy rcp(1)=1 from inactive mid lanes, folded into 127).
//   loads:  sector-packed scalar gather via __ldg (.nc), 37 lines/row
//           (= irreducible line count), 4 striped rows/warp (MLP=16).
//   reduce: warp shfl + block smem + ONE atomicAdd per CTA.
//   graph:  memset(4B) + kernel. Measured costs of alternatives:
//           per-warp same-addr atomics +4.3us, in-kernel finalize +0.6us,
//           dependent reduce-kernel node +0.9us.
//   floor:  warm-L2 line service (~7.5us) + launch/ramp (~2.5us).

__device__ __forceinline__ float fast_rcp(float x) {
    float r;
    asm("rcp.approx.ftz.f32 %0, %1;" : "=f"(r) : "f"(x));
    return r;
}

// Fold 4 reciprocals into one MUFU.RCP:
//   1/h+1/t+1/m0+1/m1 = ((h+t)*m0*m1 + (m0+m1)*h*t) * rcp(h*t*m0*m1)
__device__ __forceinline__ float fold4(float h, float t, float m0, float m1) {
    const float a   = h * t;
    const float b   = m0 * m1;
    const float num = (h + t) * b + (m0 + m1) * a;
    return num * fast_rcp(a * b);
}

__global__ __launch_bounds__(256)
void fuzzy_chain_kernel(const float* __restrict__ maze, float* __restrict__ out)
{
    const int warp_local  = threadIdx.x >> 5;                 // 0..7
    const int warp_global = blockIdx.x * 8 + warp_local;
    const int lane        = threadIdx.x & 31;

    // ---- per-lane scalar indices (shared by all 4 rows) ------------------
    int h_i = 4 * lane + 1;
    if (lane == 0) h_i = 1;
    if (lane == 1) h_i = 6;

    int t_i = 3717 + 4 * lane;
    if (lane == 29) t_i = 3721;                   // duplicate 3721
    if (lane == 30) t_i = 3839;
    if (lane == 31) t_i = 3841;

    const int k     = lane >> 1;
    const int comp  = lane & 1;
    const int p1    = 16 + k;
    const bool act1 = (p1 < 28);
    const int m0_i  = 124 * k + 245 + 4 * comp;
    const int m1_i  = 124 * (act1 ? p1 : 27) + 245 + 4 * comp;

    const float* __restrict__ r0 = maze + (size_t)warp_global * MAZE_LEN;
    const float* __restrict__ r1 = r0 + (size_t)NWARPS * MAZE_LEN;
    const float* __restrict__ r2 = r1 + (size_t)NWARPS * MAZE_LEN;
    const float* __restrict__ r3 = r2 + (size_t)NWARPS * MAZE_LEN;

    // ---- front-batch all 16 scalar loads (LDG.E.NC, MLP=16) --------------
    const float h0 = __ldg(r0 + h_i), t0 = __ldg(r0 + t_i);
    const float a0 = __ldg(r0 + m0_i), b0l = __ldg(r0 + m1_i);
    const float h1 = __ldg(r1 + h_i), t1 = __ldg(r1 + t_i);
    const float a1 = __ldg(r1 + m0_i), b1l = __ldg(r1 + m1_i);
    const float h2 = __ldg(r2 + h_i), t2 = __ldg(r2 + t_i);
    const float a2 = __ldg(r2 + m0_i), b2l = __ldg(r2 + m1_i);
    const float h3 = __ldg(r3 + h_i), t3 = __ldg(r3 + t_i);
    const float a3 = __ldg(r3 + m0_i), b3l = __ldg(r3 + m1_i);

    const float b0 = act1 ? b0l : 1.0f;           // dummy -> rcp(1)=1, in constant
    const float b1 = act1 ? b1l : 1.0f;
    const float b2 = act1 ? b2l : 1.0f;
    const float b3 = act1 ? b3l : 1.0f;

    float s0 = fold4(h0, t0, a0, b0);
    float s1 = fold4(h1, t1, a1, b1);
    float s2 = fold4(h2, t2, a2, b2);
    float s3 = fold4(h3, t3, a3, b3);

    // ---- warp reduction of all 4 rows' S ---------------------------------
    #pragma unroll
    for (int off = 16; off > 0; off >>= 1) {
        s0 += __shfl_xor_sync(0xffffffffu, s0, off);
        s1 += __shfl_xor_sync(0xffffffffu, s1, off);
        s2 += __shfl_xor_sync(0xffffffffu, s2, off);
        s3 += __shfl_xor_sync(0xffffffffu, s3, off);
    }

    __shared__ float warp_vals[8];
    if (lane == 0) {
        // x==0 -> inf -> log(inf)=inf -> fminf -> 90; two zeros -> NaN ->
        // fminf(NaN,90)=90 (matches the reference clip exactly).
        const float v0 = fminf(logf(s0 - 127.0f), 90.0f);
        const float v1 = fminf(logf(s1 - 127.0f), 90.0f);
        const float v2 = fminf(logf(s2 - 127.0f), 90.0f);
        const float v3 = fminf(logf(s3 - 127.0f), 90.0f);
        warp_vals[warp_local] = (v0 + v1) + (v2 + v3);
    }
    __syncthreads();

    if (threadIdx.x == 0) {
        float t = 0.0f;
        #pragma unroll
        for (int i = 0; i < 8; i++) t += warp_vals[i];
        atomicAdd(out, t * (1.0f / (float)BATCH));   // exact power-of-two scale
    }
}

extern "C" void kernel_launch(void* const* d_in, const int* in_sizes, int n_in,
                              void* d_out, int out_size)
{
    const float* maze = (const float*)d_in[0];
    float*       out  = (float*)d_out;

    cudaMemsetAsync(out, 0, sizeof(float), 0);      // overlaps kernel ramp

    const int blocks = NWARPS / 8;                  // 512 CTAs, 256 threads each
    fuzzy_chain_kernel<<<blocks, 256>>>(maze, out);
}